// round 10
// baseline (speedup 1.0000x reference)
#include <cuda_runtime.h>
#include <cuda_fp16.h>
#include <cstdint>

#define NPTS    16384
#define NBINS   256
#define NSLICE  16
#define SLICEN  (NPTS/NSLICE)      // 1024 targets per slice
#define TPB     256
#define QPB     256                // queries per tile
#define QT      (NPTS/QPB)         // 64 tiles per direction
#define GRID_H  (2*NPTS/TPB)       // 128 hist blocks
#define GRID_S  (2*QT*NSLICE)      // 2048 solve blocks
#define XLO     (-8.0f)
#define XWIDTH  (16.0f/NBINS)

// ---- pipeline state; everything transient is re-initialized each replay ----
__device__ int      g_hist[2][NBINS];
__device__ int      g_start[2][NBINS + 1];
__device__ int      g_cursor[2][NBINS];
__device__ unsigned g_exlo[2][NSLICE], g_exhi[2][NSLICE];
__device__ float4   g_pts[2][NPTS];          // sorted (x,y,z, orig_idx bits)
__device__ uint4    g_frag[2][NPTS][2];      // target B-fragments, sorted order
__device__ unsigned g_best[2][NPTS];         // per-row best (encoded), atomicMin
__device__ unsigned g_tick1, g_tick2;

static __device__ __forceinline__ unsigned enc_f(float f) {
    unsigned u = __float_as_uint(f);
    return (u & 0x80000000u) ? ~u : (u | 0x80000000u);
}
static __device__ __forceinline__ float dec_f(unsigned u) {
    unsigned b = (u & 0x80000000u) ? (u & 0x7fffffffu) : ~u;
    return __uint_as_float(b);
}
static __device__ __forceinline__ unsigned pkh2(__half lo, __half hi) {
    __half2 h = __halves2half2(lo, hi);
    return *reinterpret_cast<unsigned*>(&h);
}

// m16n8k16 fp16 MMA, fp32 accumulate. A row-major, B col-major.
#define MMA_F16(d0,d1,d2,d3, a0,a1,a2,a3, b0,b1, c0,c1,c2,c3)                       \
    asm("mma.sync.aligned.m16n8k16.row.col.f32.f16.f16.f32 "                        \
        "{%0,%1,%2,%3}, {%4,%5,%6,%7}, {%8,%9}, {%10,%11,%12,%13};"                 \
        : "=f"(d0), "=f"(d1), "=f"(d2), "=f"(d3)                                    \
        : "r"(a0), "r"(a1), "r"(a2), "r"(a3), "r"(b0), "r"(b1),                     \
          "f"(c0), "f"(c1), "f"(c2), "f"(c3))

// ============================================================================
// 1) hist + best-init; LAST block (ticket) runs the prefix-scan inline and
//    re-zeros hist/cursor + inits slice-range accumulators for next replay.
// ============================================================================
__global__ void __launch_bounds__(TPB)
k_histscan(const float* __restrict__ adv, const float* __restrict__ ori) {
    __shared__ int amLast;
    int tid = threadIdx.x;
    int i = blockIdx.x * TPB + tid;
    int c = i >> 14, idx = i & (NPTS - 1);
    const float* src = c ? ori : adv;
    float x = src[3 * idx];
    int bin = min(max((int)((x - XLO) * (1.0f / XWIDTH)), 0), NBINS - 1);
    atomicAdd(&g_hist[c][bin], 1);
    g_best[c][idx] = 0xFF800000u;   // enc(+inf)

    __threadfence();
    if (tid == 0) amLast = (atomicAdd(&g_tick1, 1u) == GRID_H - 1);
    __syncthreads();
    if (!amLast) return;
    if (tid == 0) g_tick1 = 0;
    __threadfence();
    if (tid < 64) {
        int lane = tid & 31, cc = tid >> 5;
        int h[8], s8 = 0;
#pragma unroll
        for (int k = 0; k < 8; k++) { h[k] = g_hist[cc][lane * 8 + k]; s8 += h[k]; }
        int incl = s8;
#pragma unroll
        for (int off = 1; off < 32; off <<= 1) {
            int v = __shfl_up_sync(0xffffffffu, incl, off);
            if (lane >= off) incl += v;
        }
        int run = incl - s8;
#pragma unroll
        for (int k = 0; k < 8; k++) { g_start[cc][lane * 8 + k] = run; run += h[k]; }
        if (lane == 31) g_start[cc][NBINS] = run;
#pragma unroll
        for (int k = 0; k < 8; k++) {
            g_hist[cc][lane * 8 + k]   = 0;
            g_cursor[cc][lane * 8 + k] = 0;
        }
        if (lane < NSLICE) { g_exlo[cc][lane] = 0xFFFFFFFFu; g_exhi[cc][lane] = 0u; }
    }
}

// ============================================================================
// 2) counting-sort scatter: sorted points + fp16-split B fragments + exact
//    slice x-ranges via encoded min/max atomics.
// ============================================================================
__global__ void k_scatter(const float* __restrict__ adv, const float* __restrict__ ori) {
    int i = blockIdx.x * blockDim.x + threadIdx.x;
    int c = i >> 14, idx = i & (NPTS - 1);
    const float* src = c ? ori : adv;
    float x = src[3 * idx], y = src[3 * idx + 1], z = src[3 * idx + 2];
    int bin = min(max((int)((x - XLO) * (1.0f / XWIDTH)), 0), NBINS - 1);
    int pos = g_start[c][bin] + atomicAdd(&g_cursor[c][bin], 1);

    g_pts[c][pos] = make_float4(x, y, z, __int_as_float(idx));
    int s = pos >> 10;              // pos / SLICEN
    unsigned ex = enc_f(x);
    atomicMin(&g_exlo[c][s], ex);
    atomicMax(&g_exhi[c][s], ex);

    __half xh = __float2half_rn(x), yh = __float2half_rn(y), zh = __float2half_rn(z);
    __half xl = __float2half_rn(x - __half2float(xh));
    __half yl = __float2half_rn(y - __half2float(yh));
    __half zl = __float2half_rn(z - __half2float(zh));
    float tq = -0.5f * (x * x + y * y + z * z);
    __half tqh = __float2half_rn(tq);
    __half tql = __float2half_rn(tq - __half2float(tqh));
    __half hz  = __float2half_rn(0.f);
    unsigned Q0 = pkh2(xh, yh), Q1 = pkh2(zh, xh), Q2 = pkh2(yh, zh);
    unsigned Q3 = pkh2(xl, yl), Q4 = pkh2(zl, tqh), Q5 = pkh2(tql, hz);
    g_frag[c][pos][0] = make_uint4(Q0, Q4, Q1, Q5);
    g_frag[c][pos][1] = make_uint4(Q2, 0u, Q3, 0u);
}

// ---- stage one query's fragments into smem (point already loaded) ----
static __device__ __forceinline__ void stage_query_p(
    float4 p, int tid, unsigned (*qA)[8], float* sQsq, int* sQid) {
    float x = p.x, y = p.y, z = p.z;
    __half xh = __float2half_rn(x), yh = __float2half_rn(y), zh = __float2half_rn(z);
    __half xl = __float2half_rn(x - __half2float(xh));
    __half yl = __float2half_rn(y - __half2float(yh));
    __half zl = __float2half_rn(z - __half2float(zh));
    __half one = __float2half_rn(1.f), hz = __float2half_rn(0.f);
    qA[tid][0] = pkh2(xh, yh);  qA[tid][1] = pkh2(zh, one);
    qA[tid][2] = pkh2(zh, xl);  qA[tid][3] = pkh2(one, hz);
    qA[tid][4] = pkh2(yl, zl);  qA[tid][5] = 0u;
    qA[tid][6] = pkh2(xh, yh);  qA[tid][7] = 0u;
    sQsq[tid] = x * x + y * y + z * z;
    sQid[tid] = __float_as_int(p.w);
}

// ============================================================================
// 3) solve: block o -> (step, dir, qt); step = rank of slice by distance from
//    home. Step-0 (home) blocks dispatch first and establish g_best; later
//    waves prune against it (stale-high bound = conservative, never wrong).
//    LAST block (ticket) reduces g_best to the chamfer scalar.
// ============================================================================
__global__ void __launch_bounds__(TPB)
k_solve(float* __restrict__ out) {
    __shared__ uint4    sB4[SLICEN * 2];   // 32 KB
    __shared__ unsigned qA[QPB][8];        // 8 KB
    __shared__ float    sQsq[QPB];
    __shared__ int      sQid[QPB];
    __shared__ int      amLast;

    int o = blockIdx.x;
    int step = o >> 7;            // 0..15 (rank)
    int rem  = o & 127;
    int dir = rem >> 6, qt = rem & 63;
    int qc = dir, tc = 1 - dir;
    int tid = threadIdx.x;
    int warp = tid >> 5;
    int home = qt >> 2;

    // rank -> slice: enumerate deltas 0,+1,-1,+2,-2,... skipping out-of-range
    int sp = home;
    if (step > 0) {
        int r = 0;
#pragma unroll
        for (int k = 1; k <= 30; k++) {
            int d = ((k + 1) >> 1) * ((k & 1) ? 1 : -1);
            int cand = home + d;
            if (cand >= 0 && cand < NSLICE) {
                r++;
                if (r == step) { sp = cand; break; }
            }
        }
    }

    // ---- prologue: own query point; per-warp bound from current g_best ----
    float4 p = g_pts[qc][qt * QPB + tid];
    int pruned = 0;
    if (step > 0) {
        float bnd = dec_f(g_best[dir][__float_as_int(p.w)]);
        float wlo = p.x, whi = p.x;
#pragma unroll
        for (int off = 16; off >= 1; off >>= 1) {
            bnd = fmaxf(bnd, __shfl_xor_sync(0xffffffffu, bnd, off));
            wlo = fminf(wlo, __shfl_xor_sync(0xffffffffu, wlo, off));
            whi = fmaxf(whi, __shfl_xor_sync(0xffffffffu, whi, off));
        }
        float slo = dec_f(g_exlo[tc][sp]), shi = dec_f(g_exhi[tc][sp]);
        float gap = fmaxf(0.f, fmaxf(slo - whi, wlo - shi));
        pruned = (gap * gap > bnd + 1e-3f);
    }

    if (!__syncthreads_and(pruned)) {
        stage_query_p(p, tid, qA, sQsq, sQid);
        {
            int tb = sp * SLICEN;
            for (int k = tid; k < SLICEN * 2; k += TPB)
                sB4[k] = g_frag[tc][tb + (k >> 1)][k & 1];
        }
        __syncthreads();

        if (!pruned) {
            int lane = tid & 31;
            int gid = lane >> 2, tl = lane & 3;
            int lr = warp * 32 + gid;
            uint2 u0 = *reinterpret_cast<const uint2*>(&qA[lr +  0][2 * tl]);
            uint2 u1 = *reinterpret_cast<const uint2*>(&qA[lr +  8][2 * tl]);
            uint2 u2 = *reinterpret_cast<const uint2*>(&qA[lr + 16][2 * tl]);
            uint2 u3 = *reinterpret_cast<const uint2*>(&qA[lr + 24][2 * tl]);

            float ninf = __int_as_float(0xFF800000);
            float mx00 = ninf, mx01 = ninf, mx10 = ninf, mx11 = ninf;
            const float zf = 0.0f;
            const uint2* sb = reinterpret_cast<const uint2*>(sB4);
#pragma unroll 4
            for (int j = 0; j < SLICEN; j += 8) {
                uint2 bb = sb[(j + gid) * 4 + tl];
                float d0, d1, d2, d3;
                MMA_F16(d0, d1, d2, d3, u0.x, u1.x, u0.y, u1.y, bb.x, bb.y, zf, zf, zf, zf);
                mx00 = fmaxf(mx00, fmaxf(d0, d1));
                mx01 = fmaxf(mx01, fmaxf(d2, d3));
                MMA_F16(d0, d1, d2, d3, u2.x, u3.x, u2.y, u3.y, bb.x, bb.y, zf, zf, zf, zf);
                mx10 = fmaxf(mx10, fmaxf(d0, d1));
                mx11 = fmaxf(mx11, fmaxf(d2, d3));
            }
#pragma unroll
            for (int off = 1; off <= 2; off <<= 1) {
                mx00 = fmaxf(mx00, __shfl_xor_sync(0xffffffffu, mx00, off));
                mx01 = fmaxf(mx01, __shfl_xor_sync(0xffffffffu, mx01, off));
                mx10 = fmaxf(mx10, __shfl_xor_sync(0xffffffffu, mx10, off));
                mx11 = fmaxf(mx11, __shfl_xor_sync(0xffffffffu, mx11, off));
            }
            if (tl == 0) {
                atomicMin(&g_best[dir][sQid[lr +  0]], enc_f(fmaf(-2.f, mx00, sQsq[lr +  0])));
                atomicMin(&g_best[dir][sQid[lr +  8]], enc_f(fmaf(-2.f, mx01, sQsq[lr +  8])));
                atomicMin(&g_best[dir][sQid[lr + 16]], enc_f(fmaf(-2.f, mx10, sQsq[lr + 16])));
                atomicMin(&g_best[dir][sQid[lr + 24]], enc_f(fmaf(-2.f, mx11, sQsq[lr + 24])));
            }
        }
    }

    // ---- ticket: last of all GRID_S blocks reduces g_best -> scalar ----
    __threadfence();
    __syncthreads();
    if (tid == 0) amLast = (atomicAdd(&g_tick2, 1u) == GRID_S - 1);
    __syncthreads();
    if (!amLast) return;
    if (tid == 0) g_tick2 = 0;   // replay reset
    __threadfence();

    float s = 0.f;
    const unsigned* gb = &g_best[0][0];
    for (int k = tid; k < 2 * NPTS; k += TPB) s += dec_f(__ldcg(&gb[k]));
    sQsq[tid] = s;               // reuse smem
    __syncthreads();
    for (int k = TPB / 2; k > 0; k >>= 1) {
        if (tid < k) sQsq[tid] += sQsq[tid + k];
        __syncthreads();
    }
    if (tid == 0) out[0] = sQsq[0] / (float)NPTS;
}

extern "C" void kernel_launch(void* const* d_in, const int* in_sizes, int n_in,
                              void* d_out, int out_size) {
    const float* adv = (const float*)d_in[0];
    const float* ori = (const float*)d_in[1];
    k_histscan<<<GRID_H, TPB>>>(adv, ori);
    k_scatter<<<GRID_H, TPB>>>(adv, ori);
    k_solve<<<GRID_S, TPB>>>((float*)d_out);
}